// round 1
// baseline (speedup 1.0000x reference)
#include <cuda_runtime.h>
#include <math.h>

// Problem shapes (fixed for this problem instance)
#define NX 4096
#define NY 16384
#define CX 128
#define CY 128
#define OD 256
#define KIN 256        // CX + CY
#define NBATCH 8

#define BIGD 1e30f
#define W_EPS 1e-16f
#define LN_EPS 1e-5f

// Scratch: interpolated features [NY, CX]  (8 MB, static device allocation)
__device__ float g_interp[NY * CX];

// ---------------------------------------------------------------------------
// Kernel 1: batch-masked 3-NN + inverse-distance-weighted feature interpolation
// One warp per query point.
// ---------------------------------------------------------------------------
__global__ void knn_interp_kernel(const float* __restrict__ pos_x,
                                  const float* __restrict__ xfeat,
                                  const int*   __restrict__ batch_x,
                                  const float* __restrict__ pos_y,
                                  const int*   __restrict__ batch_y)
{
    int gwarp = (blockIdx.x * blockDim.x + threadIdx.x) >> 5;
    int lane  = threadIdx.x & 31;
    if (gwarp >= NY) return;
    const int yi = gwarp;

    const float py0 = pos_y[yi * 3 + 0];
    const float py1 = pos_y[yi * 3 + 1];
    const float py2 = pos_y[yi * 3 + 2];
    const float ny2 = py0 * py0 + py1 * py1 + py2 * py2;
    const int b = batch_y[yi];

    // batch_x is sorted: binary search for [start, end) of batch b
    int lo = 0, hi = NX;
    while (lo < hi) { int m = (lo + hi) >> 1; if (batch_x[m] <  b) lo = m + 1; else hi = m; }
    const int s = lo;
    lo = s; hi = NX;
    while (lo < hi) { int m = (lo + hi) >> 1; if (batch_x[m] <= b) lo = m + 1; else hi = m; }
    const int e = lo;

    // per-lane top-3 (sorted ascending by (d2, idx) lexicographic)
    float d0 = BIGD, d1 = BIGD, d2v = BIGD;
    int   i0 = 0,    i1 = 0,    i2 = 0;

#define INSERT(dd, jj)                                                          \
    do {                                                                        \
        float _d = (dd); int _j = (jj);                                         \
        if (_d < d0 || (_d == d0 && _j < i0)) {                                 \
            d2v = d1; i2 = i1; d1 = d0; i1 = i0; d0 = _d; i0 = _j;              \
        } else if (_d < d1 || (_d == d1 && _j < i1)) {                          \
            d2v = d1; i2 = i1; d1 = _d; i1 = _j;                                \
        } else if (_d < d2v || (_d == d2v && _j < i2)) {                        \
            d2v = _d; i2 = _j;                                                  \
        }                                                                       \
    } while (0)

    for (int j = s + lane; j < e; j += 32) {
        float px0 = pos_x[j * 3 + 0];
        float px1 = pos_x[j * 3 + 1];
        float px2 = pos_x[j * 3 + 2];
        float nx2 = px0 * px0 + px1 * px1 + px2 * px2;
        float dot = py0 * px0 + py1 * px1 + py2 * px2;
        float d = ny2 + nx2 - 2.0f * dot;       // same expansion as reference
        d = fmaxf(d, 0.0f);
        INSERT(d, j);
    }

    // butterfly merge: top-3 merge is associative+commutative, so all lanes
    // converge to the global top-3 (no broadcast needed afterwards)
    for (int off = 16; off; off >>= 1) {
        float od0 = __shfl_xor_sync(0xffffffffu, d0,  off);
        float od1 = __shfl_xor_sync(0xffffffffu, d1,  off);
        float od2 = __shfl_xor_sync(0xffffffffu, d2v, off);
        int   oi0 = __shfl_xor_sync(0xffffffffu, i0,  off);
        int   oi1 = __shfl_xor_sync(0xffffffffu, i1,  off);
        int   oi2 = __shfl_xor_sync(0xffffffffu, i2,  off);
        INSERT(od0, oi0);
        INSERT(od1, oi1);
        INSERT(od2, oi2);
    }
#undef INSERT

    const float w0 = 1.0f / fmaxf(d0,  W_EPS);
    const float w1 = 1.0f / fmaxf(d1,  W_EPS);
    const float w2 = 1.0f / fmaxf(d2v, W_EPS);
    const float inv_wsum = 1.0f / (w0 + w1 + w2);

    const float* f0 = xfeat + (size_t)i0 * CX;
    const float* f1 = xfeat + (size_t)i1 * CX;
    const float* f2 = xfeat + (size_t)i2 * CX;
    float* outp = g_interp + (size_t)yi * CX;
    for (int c = lane; c < CX; c += 32) {
        float v = w0 * f0[c] + w1 * f1[c] + w2 * f2[c];
        outp[c] = v * inv_wsum;
    }
}

// ---------------------------------------------------------------------------
// Kernel 2: h = concat(interp, y) @ W.T  -> LayerNorm -> ReLU
// Tiled GEMM: 64 rows x 256 outs per block, K=256 staged in shared (k-major).
// ---------------------------------------------------------------------------
#define TM 64
#define TNC 64
#define SA_STRIDE 68     // 64 + 4 padding (keeps float4 alignment, spreads banks)
#define SH_STRIDE 260    // 256 + 4 padding

__global__ __launch_bounds__(256, 1)
void gemm_ln_relu_kernel(const float* __restrict__ yfeat,
                         const float* __restrict__ W,
                         const float* __restrict__ gamma,
                         const float* __restrict__ beta,
                         float* __restrict__ out)
{
    extern __shared__ float smem[];
    float* sA = smem;                         // [KIN][SA_STRIDE]  k-major A tile
    float* sW = sA + KIN * SA_STRIDE;         // [KIN][SA_STRIDE]  k-major W chunk
    float* sH = sW + KIN * SA_STRIDE;         // [TM][SH_STRIDE]

    const int tid = threadIdx.x;
    const int rowBase = blockIdx.x * TM;

    // Load A tile (concat of interp | y): coalesced global reads
    for (int idx = tid; idx < TM * KIN; idx += 256) {
        int r = idx >> 8;          // 0..63
        int k = idx & 255;         // 0..255
        int gr = rowBase + r;
        float v = (k < CX) ? g_interp[(size_t)gr * CX + k]
                           : yfeat[(size_t)gr * CY + (k - CX)];
        sA[k * SA_STRIDE + r] = v;
    }

    const int tx = tid & 15;       // output-col group
    const int ty = tid >> 4;       // row group
    const int r0 = ty * 4;
    const int c0 = tx * 4;

    for (int chunk = 0; chunk < OD / TNC; chunk++) {
        // Load W chunk: cols [chunk*64, chunk*64+64), all k. Coalesced reads.
        const int cbase = chunk * TNC;
        for (int idx = tid; idx < TNC * KIN; idx += 256) {
            int c = idx >> 8;      // 0..63
            int k = idx & 255;
            sW[k * SA_STRIDE + c] = W[(size_t)(cbase + c) * KIN + k];
        }
        __syncthreads();

        float acc00=0.f,acc01=0.f,acc02=0.f,acc03=0.f;
        float acc10=0.f,acc11=0.f,acc12=0.f,acc13=0.f;
        float acc20=0.f,acc21=0.f,acc22=0.f,acc23=0.f;
        float acc30=0.f,acc31=0.f,acc32=0.f,acc33=0.f;

#pragma unroll 4
        for (int k = 0; k < KIN; k++) {
            float4 a = *(const float4*)&sA[k * SA_STRIDE + r0];
            float4 w = *(const float4*)&sW[k * SA_STRIDE + c0];
            acc00 += a.x * w.x; acc01 += a.x * w.y; acc02 += a.x * w.z; acc03 += a.x * w.w;
            acc10 += a.y * w.x; acc11 += a.y * w.y; acc12 += a.y * w.z; acc13 += a.y * w.w;
            acc20 += a.z * w.x; acc21 += a.z * w.y; acc22 += a.z * w.z; acc23 += a.z * w.w;
            acc30 += a.w * w.x; acc31 += a.w * w.y; acc32 += a.w * w.z; acc33 += a.w * w.w;
        }

        float* h0 = &sH[(r0 + 0) * SH_STRIDE + cbase + c0];
        float* h1 = &sH[(r0 + 1) * SH_STRIDE + cbase + c0];
        float* h2 = &sH[(r0 + 2) * SH_STRIDE + cbase + c0];
        float* h3 = &sH[(r0 + 3) * SH_STRIDE + cbase + c0];
        h0[0]=acc00; h0[1]=acc01; h0[2]=acc02; h0[3]=acc03;
        h1[0]=acc10; h1[1]=acc11; h1[2]=acc12; h1[3]=acc13;
        h2[0]=acc20; h2[1]=acc21; h2[2]=acc22; h2[3]=acc23;
        h3[0]=acc30; h3[1]=acc31; h3[2]=acc32; h3[3]=acc33;
        __syncthreads();
    }

    // LayerNorm + ReLU: 4 threads per row, 64 cols each (interleaved float4s)
    const int row = tid >> 2;       // 0..63
    const int jj  = tid & 3;        // 0..3
    float sum = 0.f, sumsq = 0.f;
#pragma unroll
    for (int i = 0; i < 16; i++) {
        float4 v = *(const float4*)&sH[row * SH_STRIDE + jj * 4 + i * 16];
        sum   += v.x + v.y + v.z + v.w;
        sumsq += v.x * v.x + v.y * v.y + v.z * v.z + v.w * v.w;
    }
    sum   += __shfl_xor_sync(0xffffffffu, sum,   1);
    sumsq += __shfl_xor_sync(0xffffffffu, sumsq, 1);
    sum   += __shfl_xor_sync(0xffffffffu, sum,   2);
    sumsq += __shfl_xor_sync(0xffffffffu, sumsq, 2);

    const float mu  = sum * (1.0f / OD);
    float var = sumsq * (1.0f / OD) - mu * mu;
    var = fmaxf(var, 0.0f);
    const float rstd = rsqrtf(var + LN_EPS);

    const int grow = rowBase + row;
#pragma unroll
    for (int i = 0; i < 16; i++) {
        int c = jj * 4 + i * 16;
        float4 v  = *(const float4*)&sH[row * SH_STRIDE + c];
        float4 g  = *(const float4*)&gamma[c];
        float4 be = *(const float4*)&beta[c];
        v.x = fmaxf((v.x - mu) * rstd * g.x + be.x, 0.0f);
        v.y = fmaxf((v.y - mu) * rstd * g.y + be.y, 0.0f);
        v.z = fmaxf((v.z - mu) * rstd * g.z + be.z, 0.0f);
        v.w = fmaxf((v.w - mu) * rstd * g.w + be.w, 0.0f);
        *(float4*)&out[(size_t)grow * OD + c] = v;
    }
}

// ---------------------------------------------------------------------------
extern "C" void kernel_launch(void* const* d_in, const int* in_sizes, int n_in,
                              void* d_out, int out_size)
{
    const float* pos_x   = (const float*)d_in[0];   // [NX,3]
    const float* xfeat   = (const float*)d_in[1];   // [NX,CX]
    const int*   batch_x = (const int*)  d_in[2];   // [NX]
    const float* pos_y   = (const float*)d_in[3];   // [NY,3]
    const float* yfeat   = (const float*)d_in[4];   // [NY,CY]
    const int*   batch_y = (const int*)  d_in[5];   // [NY]
    const float* W       = (const float*)d_in[6];   // [OD,KIN]
    const float* gamma   = (const float*)d_in[7];   // [OD]
    const float* beta    = (const float*)d_in[8];   // [OD]
    float* out = (float*)d_out;                     // [NY,OD]

    // Kernel 1: one warp per query point
    {
        int threads = 256;
        int blocks = (NY * 32) / threads;           // 2048
        knn_interp_kernel<<<blocks, threads>>>(pos_x, xfeat, batch_x, pos_y, batch_y);
    }

    // Kernel 2: fused GEMM + LayerNorm + ReLU
    {
        size_t smem_bytes = (size_t)(2 * KIN * SA_STRIDE + TM * SH_STRIDE) * sizeof(float);
        cudaFuncSetAttribute(gemm_ln_relu_kernel,
                             cudaFuncAttributeMaxDynamicSharedMemorySize,
                             (int)smem_bytes);
        gemm_ln_relu_kernel<<<NY / TM, 256, smem_bytes>>>(yfeat, W, gamma, beta, out);
    }
}

// round 3
// speedup vs baseline: 2.2060x; 2.2060x over previous
#include <cuda_runtime.h>
#include <cuda_bf16.h>
#include <cstdint>
#include <math.h>

// Problem shapes (fixed)
#define NX 4096
#define NY 16384
#define CX 128
#define CY 128
#define OD 256
#define KIN 256
#define BIGD 1e30f
#define W_EPS 1e-16f
#define LN_EPS 1e-5f

// Global scratch
__device__ float g_interp[NY * CX];          // 8 MB
__device__ __nv_bfloat16 g_Wh[OD * KIN];     // W hi split
__device__ __nv_bfloat16 g_Wl[OD * KIN];     // W lo split

// ---------------------------------------------------------------------------
// Helpers (all baseline-PTX instructions: sm_80+, valid for compute_100)
// ---------------------------------------------------------------------------
static __device__ __forceinline__ uint32_t smem_u32(const void* p) {
    uint32_t a;
    asm("{ .reg .u64 t; cvta.to.shared.u64 t, %1; cvt.u32.u64 %0, t; }"
        : "=r"(a) : "l"(p));
    return a;
}

static __device__ __forceinline__ void ldsm_x4(uint32_t addr, uint32_t& r0, uint32_t& r1,
                                               uint32_t& r2, uint32_t& r3) {
    asm volatile("ldmatrix.sync.aligned.m8n8.x4.shared.b16 {%0,%1,%2,%3}, [%4];"
                 : "=r"(r0), "=r"(r1), "=r"(r2), "=r"(r3) : "r"(addr));
}

static __device__ __forceinline__ void mma_bf16(float* d, uint32_t a0, uint32_t a1,
                                                uint32_t a2, uint32_t a3,
                                                uint32_t b0, uint32_t b1) {
    asm volatile(
        "mma.sync.aligned.m16n8k16.row.col.f32.bf16.bf16.f32 "
        "{%0,%1,%2,%3},{%4,%5,%6,%7},{%8,%9},{%0,%1,%2,%3};"
        : "+f"(d[0]), "+f"(d[1]), "+f"(d[2]), "+f"(d[3])
        : "r"(a0), "r"(a1), "r"(a2), "r"(a3), "r"(b0), "r"(b1));
}

static __device__ __forceinline__ void cp_async16(uint32_t dst, const void* src) {
    asm volatile("cp.async.cg.shared.global [%0], [%1], 16;" :: "r"(dst), "l"(src));
}
static __device__ __forceinline__ void cp_commit() {
    asm volatile("cp.async.commit_group;" ::: "memory");
}
template <int N>
static __device__ __forceinline__ void cp_wait() {
    asm volatile("cp.async.wait_group %0;" :: "n"(N) : "memory");
}

// ---------------------------------------------------------------------------
// Kernel 0: split W into bf16 hi/lo
// ---------------------------------------------------------------------------
__global__ void prep_w_kernel(const float* __restrict__ W) {
    int i = blockIdx.x * blockDim.x + threadIdx.x;
    if (i < OD * KIN) {
        float v = W[i];
        __nv_bfloat16 h = __float2bfloat16_rn(v);
        g_Wh[i] = h;
        g_Wl[i] = __float2bfloat16_rn(v - __bfloat162float(h));
    }
}

// ---------------------------------------------------------------------------
// Kernel 1: batch-masked 3-NN + IDW interpolation (one warp per query)
// ---------------------------------------------------------------------------
__global__ void knn_interp_kernel(const float* __restrict__ pos_x,
                                  const float* __restrict__ xfeat,
                                  const int*   __restrict__ batch_x,
                                  const float* __restrict__ pos_y,
                                  const int*   __restrict__ batch_y)
{
    int gwarp = (blockIdx.x * blockDim.x + threadIdx.x) >> 5;
    int lane  = threadIdx.x & 31;
    if (gwarp >= NY) return;
    const int yi = gwarp;

    const float py0 = pos_y[yi * 3 + 0];
    const float py1 = pos_y[yi * 3 + 1];
    const float py2 = pos_y[yi * 3 + 2];
    const float ny2 = py0 * py0 + py1 * py1 + py2 * py2;
    const int b = batch_y[yi];

    int lo = 0, hi = NX;
    while (lo < hi) { int m = (lo + hi) >> 1; if (batch_x[m] <  b) lo = m + 1; else hi = m; }
    const int s = lo;
    lo = s; hi = NX;
    while (lo < hi) { int m = (lo + hi) >> 1; if (batch_x[m] <= b) lo = m + 1; else hi = m; }
    const int e = lo;

    float d0 = BIGD, d1 = BIGD, d2v = BIGD;
    int   i0 = 0,    i1 = 0,    i2 = 0;

#define INSERT(dd, jj)                                                          \
    do {                                                                        \
        float _d = (dd); int _j = (jj);                                         \
        if (_d < d0 || (_d == d0 && _j < i0)) {                                 \
            d2v = d1; i2 = i1; d1 = d0; i1 = i0; d0 = _d; i0 = _j;              \
        } else if (_d < d1 || (_d == d1 && _j < i1)) {                          \
            d2v = d1; i2 = i1; d1 = _d; i1 = _j;                                \
        } else if (_d < d2v || (_d == d2v && _j < i2)) {                        \
            d2v = _d; i2 = _j;                                                  \
        }                                                                       \
    } while (0)

    for (int j = s + lane; j < e; j += 32) {
        float px0 = pos_x[j * 3 + 0];
        float px1 = pos_x[j * 3 + 1];
        float px2 = pos_x[j * 3 + 2];
        float nx2 = px0 * px0 + px1 * px1 + px2 * px2;
        float dot = py0 * px0 + py1 * px1 + py2 * px2;
        float d = fmaxf(ny2 + nx2 - 2.0f * dot, 0.0f);
        INSERT(d, j);
    }
    for (int off = 16; off; off >>= 1) {
        float od0 = __shfl_xor_sync(0xffffffffu, d0,  off);
        float od1 = __shfl_xor_sync(0xffffffffu, d1,  off);
        float od2 = __shfl_xor_sync(0xffffffffu, d2v, off);
        int   oi0 = __shfl_xor_sync(0xffffffffu, i0,  off);
        int   oi1 = __shfl_xor_sync(0xffffffffu, i1,  off);
        int   oi2 = __shfl_xor_sync(0xffffffffu, i2,  off);
        INSERT(od0, oi0);
        INSERT(od1, oi1);
        INSERT(od2, oi2);
    }
#undef INSERT

    const float w0 = 1.0f / fmaxf(d0,  W_EPS);
    const float w1 = 1.0f / fmaxf(d1,  W_EPS);
    const float w2 = 1.0f / fmaxf(d2v, W_EPS);
    const float inv_wsum = 1.0f / (w0 + w1 + w2);

    const float* f0 = xfeat + (size_t)i0 * CX;
    const float* f1 = xfeat + (size_t)i1 * CX;
    const float* f2 = xfeat + (size_t)i2 * CX;
    float* outp = g_interp + (size_t)yi * CX;
    for (int c = lane; c < CX; c += 32) {
        outp[c] = (w0 * f0[c] + w1 * f1[c] + w2 * f2[c]) * inv_wsum;
    }
}

// ---------------------------------------------------------------------------
// Kernel 2: bf16 hi/lo-split mma.sync GEMM (fp32 accum in regs) + LN + ReLU
// Per CTA: 128 rows x 256 cols, K=256. 8 warps = 4(m) x 2(n).
// N processed in 8 chunks of 32 cols; accumulators for all chunks in regs.
//
// SMEM (bf16, padded stride 264 elems = 528 B for conflict-free ldmatrix):
//   A_hi [128][264]   67584 B
//   A_lo [128][264]   67584 B
//   B bufs x2: each {hi[32][264], lo[32][264]} = 33792 B   (cp.async dbl-buf)
// total 202752 B
// ---------------------------------------------------------------------------
#define SAW 264                 // padded stride in bf16 units
#define SROW 528                // stride bytes
#define A_HI 0
#define A_LO 67584
#define B_BASE 135168
#define B_BUF 33792             // one buffer (hi+lo)
#define B_LOOF 16896            // lo offset within buffer
#define SM_TOTAL 202752

__global__ __launch_bounds__(256, 1)
void gemm_mma_kernel(const float* __restrict__ yfeat,
                     const float* __restrict__ gamma,
                     const float* __restrict__ beta,
                     float* __restrict__ out)
{
    extern __shared__ char smem[];
    const uint32_t sb = smem_u32(smem);

    const int tid  = threadIdx.x;
    const int wid  = tid >> 5;
    const int lane = tid & 31;
    const int g    = lane >> 2;      // mma group id (row within 8)
    const int tig  = lane & 3;       // thread in group (col pair)
    const int mw   = (wid >> 1) * 32;  // warp row base (0/32/64/96)
    const int wn   = wid & 1;          // warp n-half
    const int nb   = wn * 16;          // warp col base within 32-col chunk
    const int rowBase = blockIdx.x * 128;

    // ---- prologue: cp.async B chunk 0 ----
    {
        const int c = 0;
#pragma unroll
        for (int i = 0; i < 4; i++) {
            int idx = tid + i * 256;             // 0..1023
            int r = idx >> 5, kc = idx & 31;
            uint32_t dst = sb + B_BASE + r * SROW + kc * 16;
            cp_async16(dst,          &g_Wh[(size_t)(c * 32 + r) * KIN + kc * 8]);
            cp_async16(dst + B_LOOF, &g_Wl[(size_t)(c * 32 + r) * KIN + kc * 8]);
        }
        cp_commit();
    }

    // ---- A tile: load f32, split to bf16 hi/lo, store padded smem ----
#pragma unroll
    for (int i = 0; i < 16; i++) {
        int idx = tid + i * 256;                 // 0..4095
        int r  = idx >> 5;                       // row 0..127
        int kc = idx & 31;                       // 8-elem K chunk
        int gr = rowBase + r;
        const float* src = (kc < 16) ? &g_interp[(size_t)gr * CX + kc * 8]
                                     : &yfeat[(size_t)gr * CY + (kc - 16) * 8];
        float4 v0 = *(const float4*)src;
        float4 v1 = *(const float4*)(src + 4);
        float v[8] = {v0.x, v0.y, v0.z, v0.w, v1.x, v1.y, v1.z, v1.w};
        uint32_t hp[4], lp[4];
#pragma unroll
        for (int j = 0; j < 4; j++) {
            __nv_bfloat16 h0 = __float2bfloat16_rn(v[2 * j]);
            __nv_bfloat16 h1 = __float2bfloat16_rn(v[2 * j + 1]);
            __nv_bfloat16 l0 = __float2bfloat16_rn(v[2 * j] - __bfloat162float(h0));
            __nv_bfloat16 l1 = __float2bfloat16_rn(v[2 * j + 1] - __bfloat162float(h1));
            hp[j] = (uint32_t)__bfloat16_as_ushort(h0) | ((uint32_t)__bfloat16_as_ushort(h1) << 16);
            lp[j] = (uint32_t)__bfloat16_as_ushort(l0) | ((uint32_t)__bfloat16_as_ushort(l1) << 16);
        }
        uint32_t off = (uint32_t)(r * SROW + kc * 16);
        *(uint4*)(smem + A_HI + off) = make_uint4(hp[0], hp[1], hp[2], hp[3]);
        *(uint4*)(smem + A_LO + off) = make_uint4(lp[0], lp[1], lp[2], lp[3]);
    }

    // ---- per-lane ldmatrix base offsets ----
    const int quad  = lane >> 3;
    const int lrow  = lane & 7;
    const int aRow  = (quad & 1) * 8 + lrow;       // within 16-row tile
    const int aKoff = (quad >> 1) * 8;
    const uint32_t offA0 = (uint32_t)((mw + aRow) * SROW + aKoff * 2);
    const uint32_t offA1 = (uint32_t)((mw + 16 + aRow) * SROW + aKoff * 2);
    const int bNrow = nb + ((lane >> 4) * 8) + lrow;
    const int bKoff = ((lane >> 3) & 1) * 8;
    const uint32_t offB = (uint32_t)(bNrow * SROW + bKoff * 2);

    float acc[8][2][2][4];
#pragma unroll
    for (int c = 0; c < 8; c++)
#pragma unroll
        for (int mt = 0; mt < 2; mt++)
#pragma unroll
            for (int nt = 0; nt < 2; nt++)
#pragma unroll
                for (int j = 0; j < 4; j++) acc[c][mt][nt][j] = 0.f;

    // ---- main loop over 8 n-chunks ----
#pragma unroll
    for (int c = 0; c < 8; c++) {
        __syncthreads();                          // prev chunk's readers done
        if (c < 7) {
            const int cn = c + 1;
#pragma unroll
            for (int i = 0; i < 4; i++) {
                int idx = tid + i * 256;
                int r = idx >> 5, kc = idx & 31;
                uint32_t dst = sb + B_BASE + (cn & 1) * B_BUF + r * SROW + kc * 16;
                cp_async16(dst,          &g_Wh[(size_t)(cn * 32 + r) * KIN + kc * 8]);
                cp_async16(dst + B_LOOF, &g_Wl[(size_t)(cn * 32 + r) * KIN + kc * 8]);
            }
            cp_commit();
            cp_wait<1>();                         // chunk c data arrived
        } else {
            cp_wait<0>();
        }
        __syncthreads();

        const uint32_t bh_base = sb + B_BASE + (c & 1) * B_BUF + offB;
        const uint32_t bl_base = bh_base + B_LOOF;
        const uint32_t ah0 = sb + A_HI + offA0;
        const uint32_t ah1 = sb + A_HI + offA1;
        const uint32_t al0 = sb + A_LO + offA0;
        const uint32_t al1 = sb + A_LO + offA1;

#pragma unroll 4
        for (int ks = 0; ks < 16; ks++) {
            const uint32_t kb = (uint32_t)(ks * 32);   // 16 bf16 = 32 B
            uint32_t Ah0[4], Ah1[4], Al0[4], Al1[4], Bh[4], Bl[4];
            ldsm_x4(ah0 + kb, Ah0[0], Ah0[1], Ah0[2], Ah0[3]);
            ldsm_x4(ah1 + kb, Ah1[0], Ah1[1], Ah1[2], Ah1[3]);
            ldsm_x4(al0 + kb, Al0[0], Al0[1], Al0[2], Al0[3]);
            ldsm_x4(al1 + kb, Al1[0], Al1[1], Al1[2], Al1[3]);
            ldsm_x4(bh_base + kb, Bh[0], Bh[1], Bh[2], Bh[3]);
            ldsm_x4(bl_base + kb, Bl[0], Bl[1], Bl[2], Bl[3]);

#pragma unroll
            for (int nt = 0; nt < 2; nt++) {
                uint32_t bh0 = Bh[nt * 2], bh1 = Bh[nt * 2 + 1];
                uint32_t bl0 = Bl[nt * 2], bl1 = Bl[nt * 2 + 1];
                mma_bf16(acc[c][0][nt], Ah0[0], Ah0[1], Ah0[2], Ah0[3], bh0, bh1);
                mma_bf16(acc[c][0][nt], Ah0[0], Ah0[1], Ah0[2], Ah0[3], bl0, bl1);
                mma_bf16(acc[c][0][nt], Al0[0], Al0[1], Al0[2], Al0[3], bh0, bh1);
                mma_bf16(acc[c][1][nt], Ah1[0], Ah1[1], Ah1[2], Ah1[3], bh0, bh1);
                mma_bf16(acc[c][1][nt], Ah1[0], Ah1[1], Ah1[2], Ah1[3], bl0, bl1);
                mma_bf16(acc[c][1][nt], Al1[0], Al1[1], Al1[2], Al1[3], bh0, bh1);
            }
        }
    }
    __syncthreads();

    // ---- LayerNorm stats (reuse B smem region) ----
    float* sSum = (float*)(smem + B_BASE);        // [128][2]
    float* sSq  = sSum + 256;                     // [128][2]
    float* sMu  = sSq + 256;                      // [128]
    float* sRs  = sMu + 128;                      // [128]

#pragma unroll
    for (int mt = 0; mt < 2; mt++)
#pragma unroll
        for (int half = 0; half < 2; half++) {
            float s = 0.f, q = 0.f;
#pragma unroll
            for (int c = 0; c < 8; c++)
#pragma unroll
                for (int nt = 0; nt < 2; nt++)
#pragma unroll
                    for (int j = 0; j < 2; j++) {
                        float v = acc[c][mt][nt][half * 2 + j];
                        s += v; q += v * v;
                    }
            s += __shfl_xor_sync(0xffffffffu, s, 1);
            q += __shfl_xor_sync(0xffffffffu, q, 1);
            s += __shfl_xor_sync(0xffffffffu, s, 2);
            q += __shfl_xor_sync(0xffffffffu, q, 2);
            if (tig == 0) {
                int row = mw + mt * 16 + half * 8 + g;
                sSum[row * 2 + wn] = s;
                sSq[row * 2 + wn]  = q;
            }
        }
    __syncthreads();

    if (tid < 128) {
        float s = sSum[tid * 2] + sSum[tid * 2 + 1];
        float q = sSq[tid * 2] + sSq[tid * 2 + 1];
        float mu = s * (1.0f / OD);
        float var = fmaxf(q * (1.0f / OD) - mu * mu, 0.0f);
        sMu[tid] = mu;
        sRs[tid] = rsqrtf(var + LN_EPS);
    }
    __syncthreads();

    // ---- normalize + affine + ReLU + store ----
#pragma unroll
    for (int mt = 0; mt < 2; mt++)
#pragma unroll
        for (int half = 0; half < 2; half++) {
            int row = mw + mt * 16 + half * 8 + g;
            float mu = sMu[row];
            float rs = sRs[row];
            float* orow = out + (size_t)(rowBase + row) * OD;
#pragma unroll
            for (int c = 0; c < 8; c++)
#pragma unroll
                for (int nt = 0; nt < 2; nt++) {
                    int col = c * 32 + nb + nt * 8 + tig * 2;
                    float2 gb0 = *(const float2*)&gamma[col];
                    float2 bb0 = *(const float2*)&beta[col];
                    float v0 = acc[c][mt][nt][half * 2 + 0];
                    float v1 = acc[c][mt][nt][half * 2 + 1];
                    float2 r2;
                    r2.x = fmaxf((v0 - mu) * rs * gb0.x + bb0.x, 0.0f);
                    r2.y = fmaxf((v1 - mu) * rs * gb0.y + bb0.y, 0.0f);
                    *(float2*)&orow[col] = r2;
                }
        }
}

// ---------------------------------------------------------------------------
extern "C" void kernel_launch(void* const* d_in, const int* in_sizes, int n_in,
                              void* d_out, int out_size)
{
    const float* pos_x   = (const float*)d_in[0];
    const float* xfeat   = (const float*)d_in[1];
    const int*   batch_x = (const int*)  d_in[2];
    const float* pos_y   = (const float*)d_in[3];
    const float* yfeat   = (const float*)d_in[4];
    const int*   batch_y = (const int*)  d_in[5];
    const float* W       = (const float*)d_in[6];
    const float* gamma   = (const float*)d_in[7];
    const float* beta    = (const float*)d_in[8];
    float* out = (float*)d_out;

    prep_w_kernel<<<(OD * KIN + 255) / 256, 256>>>(W);
    knn_interp_kernel<<<(NY * 32) / 256, 256>>>(pos_x, xfeat, batch_x, pos_y, batch_y);

    cudaFuncSetAttribute(gemm_mma_kernel,
                         cudaFuncAttributeMaxDynamicSharedMemorySize, SM_TOTAL);
    gemm_mma_kernel<<<NY / 128, 256, SM_TOTAL>>>(yfeat, gamma, beta, out);
}

// round 4
// speedup vs baseline: 2.3668x; 1.0729x over previous
#include <cuda_runtime.h>
#include <cuda_bf16.h>
#include <cstdint>
#include <math.h>

// Problem shapes (fixed)
#define NX 4096
#define NY 16384
#define CX 128
#define CY 128
#define OD 256
#define KIN 256
#define BIGD 1e30f
#define W_EPS 1e-16f
#define LN_EPS 1e-5f

// Global scratch: pre-split A (concat(interp|y)) and W, bf16 hi/lo
__device__ __nv_bfloat16 g_Ah[NY * KIN];     // 8 MB
__device__ __nv_bfloat16 g_Al[NY * KIN];     // 8 MB
__device__ __nv_bfloat16 g_Wh[OD * KIN];
__device__ __nv_bfloat16 g_Wl[OD * KIN];

// ---------------------------------------------------------------------------
// Helpers (baseline PTX, valid for compute_100)
// ---------------------------------------------------------------------------
static __device__ __forceinline__ uint32_t smem_u32(const void* p) {
    uint32_t a;
    asm("{ .reg .u64 t; cvta.to.shared.u64 t, %1; cvt.u32.u64 %0, t; }"
        : "=r"(a) : "l"(p));
    return a;
}

static __device__ __forceinline__ void ldsm_x4(uint32_t addr, uint32_t& r0, uint32_t& r1,
                                               uint32_t& r2, uint32_t& r3) {
    asm volatile("ldmatrix.sync.aligned.m8n8.x4.shared.b16 {%0,%1,%2,%3}, [%4];"
                 : "=r"(r0), "=r"(r1), "=r"(r2), "=r"(r3) : "r"(addr));
}

static __device__ __forceinline__ void mma_bf16(float* d, const uint32_t* a,
                                                uint32_t b0, uint32_t b1) {
    asm volatile(
        "mma.sync.aligned.m16n8k16.row.col.f32.bf16.bf16.f32 "
        "{%0,%1,%2,%3},{%4,%5,%6,%7},{%8,%9},{%0,%1,%2,%3};"
        : "+f"(d[0]), "+f"(d[1]), "+f"(d[2]), "+f"(d[3])
        : "r"(a[0]), "r"(a[1]), "r"(a[2]), "r"(a[3]), "r"(b0), "r"(b1));
}

static __device__ __forceinline__ void cp_async16(uint32_t dst, const void* src) {
    asm volatile("cp.async.cg.shared.global [%0], [%1], 16;" :: "r"(dst), "l"(src));
}
static __device__ __forceinline__ void cp_commit() {
    asm volatile("cp.async.commit_group;" ::: "memory");
}
template <int N>
static __device__ __forceinline__ void cp_wait() {
    asm volatile("cp.async.wait_group %0;" :: "n"(N) : "memory");
}

static __device__ __forceinline__ void split_store(float v, __nv_bfloat16* ph,
                                                   __nv_bfloat16* pl) {
    __nv_bfloat16 h = __float2bfloat16_rn(v);
    *ph = h;
    *pl = __float2bfloat16_rn(v - __bfloat162float(h));
}

// ---------------------------------------------------------------------------
// Kernel 1: KNN + interpolation + A/W bf16 hi-lo pre-split (single launch)
//   blocks [0, 2048):   one warp per query: 3-NN, IDW interp -> g_Ah/g_Al
//                        cols 0..127; also split yfeat into cols 128..255
//   blocks [2048, 2080): W split -> g_Wh/g_Wl
// ---------------------------------------------------------------------------
#define KNN_BLOCKS 2048
#define W_BLOCKS 32

__global__ void prep_kernel(const float* __restrict__ pos_x,
                            const float* __restrict__ xfeat,
                            const int*   __restrict__ batch_x,
                            const float* __restrict__ pos_y,
                            const float* __restrict__ yfeat,
                            const int*   __restrict__ batch_y,
                            const float* __restrict__ W)
{
    if (blockIdx.x >= KNN_BLOCKS) {
        int base = ((int)blockIdx.x - KNN_BLOCKS) * (256 * 8) + threadIdx.x;
#pragma unroll
        for (int i = 0; i < 8; i++) {
            int idx = base + i * 256;
            float v = W[idx];
            split_store(v, &g_Wh[idx], &g_Wl[idx]);
        }
        return;
    }

    int gwarp = (blockIdx.x * blockDim.x + threadIdx.x) >> 5;
    int lane  = threadIdx.x & 31;
    const int yi = gwarp;

    const float py0 = pos_y[yi * 3 + 0];
    const float py1 = pos_y[yi * 3 + 1];
    const float py2 = pos_y[yi * 3 + 2];
    const float ny2 = py0 * py0 + py1 * py1 + py2 * py2;
    const int b = batch_y[yi];

    int lo = 0, hi = NX;
    while (lo < hi) { int m = (lo + hi) >> 1; if (batch_x[m] <  b) lo = m + 1; else hi = m; }
    const int s = lo;
    lo = s; hi = NX;
    while (lo < hi) { int m = (lo + hi) >> 1; if (batch_x[m] <= b) lo = m + 1; else hi = m; }
    const int e = lo;

    float d0 = BIGD, d1 = BIGD, d2v = BIGD;
    int   i0 = 0,    i1 = 0,    i2 = 0;

#define INSERT(dd, jj)                                                          \
    do {                                                                        \
        float _d = (dd); int _j = (jj);                                         \
        if (_d < d0 || (_d == d0 && _j < i0)) {                                 \
            d2v = d1; i2 = i1; d1 = d0; i1 = i0; d0 = _d; i0 = _j;              \
        } else if (_d < d1 || (_d == d1 && _j < i1)) {                          \
            d2v = d1; i2 = i1; d1 = _d; i1 = _j;                                \
        } else if (_d < d2v || (_d == d2v && _j < i2)) {                        \
            d2v = _d; i2 = _j;                                                  \
        }                                                                       \
    } while (0)

    for (int j = s + lane; j < e; j += 32) {
        float px0 = pos_x[j * 3 + 0];
        float px1 = pos_x[j * 3 + 1];
        float px2 = pos_x[j * 3 + 2];
        float nx2 = px0 * px0 + px1 * px1 + px2 * px2;
        float dot = py0 * px0 + py1 * px1 + py2 * px2;
        float d = fmaxf(ny2 + nx2 - 2.0f * dot, 0.0f);
        INSERT(d, j);
    }
    for (int off = 16; off; off >>= 1) {
        float od0 = __shfl_xor_sync(0xffffffffu, d0,  off);
        float od1 = __shfl_xor_sync(0xffffffffu, d1,  off);
        float od2 = __shfl_xor_sync(0xffffffffu, d2v, off);
        int   oi0 = __shfl_xor_sync(0xffffffffu, i0,  off);
        int   oi1 = __shfl_xor_sync(0xffffffffu, i1,  off);
        int   oi2 = __shfl_xor_sync(0xffffffffu, i2,  off);
        INSERT(od0, oi0);
        INSERT(od1, oi1);
        INSERT(od2, oi2);
    }
#undef INSERT

    const float w0 = 1.0f / fmaxf(d0,  W_EPS);
    const float w1 = 1.0f / fmaxf(d1,  W_EPS);
    const float w2 = 1.0f / fmaxf(d2v, W_EPS);
    const float inv_wsum = 1.0f / (w0 + w1 + w2);

    const float* f0 = xfeat + (size_t)i0 * CX;
    const float* f1 = xfeat + (size_t)i1 * CX;
    const float* f2 = xfeat + (size_t)i2 * CX;
    const float* fy = yfeat + (size_t)yi * CY;
    __nv_bfloat16* ah = g_Ah + (size_t)yi * KIN;
    __nv_bfloat16* al = g_Al + (size_t)yi * KIN;
#pragma unroll
    for (int c0 = 0; c0 < CX; c0 += 32) {
        int c = c0 + lane;
        float v = (w0 * f0[c] + w1 * f1[c] + w2 * f2[c]) * inv_wsum;
        split_store(v, &ah[c], &al[c]);
        split_store(fy[c], &ah[CX + c], &al[CX + c]);
    }
}

// ---------------------------------------------------------------------------
// Kernel 2: bf16 hi/lo-split mma.sync GEMM + LN + ReLU
// Per CTA: 128 rows x 256 cols, K=256. 8 warps = 4(m) x 2(n), warp tile 32x32.
// N in 4 chunks of 64; each chunk in 2 phases (Bh: AhBh+AlBh, Bl: AhBl),
// phases double-buffered via cp.async.
//
// SMEM (padded stride 528 B for conflict-free ldmatrix):
//   A_hi [128][264bf16]   67584 B   @ 0
//   A_lo [128][264bf16]   67584 B   @ 67584
//   Bbuf x2 [64][264bf16] 33792 B   @ 135168 / 168960
// total 202752 B
// ---------------------------------------------------------------------------
#define SROW 528
#define A_HI 0
#define A_LO 67584
#define B_BASE 135168
#define B_BUF 33792
#define SM_TOTAL 202752

__global__ __launch_bounds__(256, 1)
void gemm_mma_kernel(const float* __restrict__ gamma,
                     const float* __restrict__ beta,
                     float* __restrict__ out)
{
    extern __shared__ char smem[];
    const uint32_t sb = smem_u32(smem);

    const int tid  = threadIdx.x;
    const int wid  = tid >> 5;
    const int lane = tid & 31;
    const int g    = lane >> 2;
    const int tig  = lane & 3;
    const int mw   = (wid >> 1) * 32;      // warp row base
    const int wn   = wid & 1;              // warp n-half (32 cols)
    const int rowBase = blockIdx.x * 128;

    // ---- prologue: cp.async A (hi+lo) and B phase 0 (Wh chunk 0) ----
    {
        // A: 128 rows x 32 x 16B per precision
#pragma unroll
        for (int i = 0; i < 16; i++) {
            int idx = tid + i * 256;           // 0..4095
            int r = idx >> 5, kc = idx & 31;
            const size_t gs = (size_t)(rowBase + r) * KIN + kc * 8;
            uint32_t off = (uint32_t)(r * SROW + kc * 16);
            cp_async16(sb + A_HI + off, &g_Ah[gs]);
            cp_async16(sb + A_LO + off, &g_Al[gs]);
        }
        // B phase 0: rows 0..63 of Wh
#pragma unroll
        for (int i = 0; i < 8; i++) {
            int idx = tid + i * 256;           // 0..2047
            int r = idx >> 5, kc = idx & 31;
            cp_async16(sb + B_BASE + (uint32_t)(r * SROW + kc * 16),
                       &g_Wh[(size_t)r * KIN + kc * 8]);
        }
        cp_commit();
    }

    // ---- per-lane ldmatrix offsets ----
    const int quad  = lane >> 3;
    const int lrow  = lane & 7;
    const int aRow  = (quad & 1) * 8 + lrow;
    const int aKoff = (quad >> 1) * 8;
    const uint32_t offA0 = (uint32_t)((mw + aRow) * SROW + aKoff * 2);
    const uint32_t offA1 = (uint32_t)((mw + 16 + aRow) * SROW + aKoff * 2);
    const int bRow  = ((lane >> 4) * 8) + lrow;
    const int bKoff = ((lane >> 3) & 1) * 8;
    const uint32_t offB0 = (uint32_t)((wn * 32 + bRow) * SROW + bKoff * 2);
    const uint32_t offB1 = offB0 + 16 * SROW;

    float acc[4][2][4][4];
#pragma unroll
    for (int c = 0; c < 4; c++)
#pragma unroll
        for (int mt = 0; mt < 2; mt++)
#pragma unroll
            for (int nt = 0; nt < 4; nt++)
#pragma unroll
                for (int j = 0; j < 4; j++) acc[c][mt][nt][j] = 0.f;

    // ---- main loop: 8 phases (chunk = p>>1, kind = p&1: 0=Wh, 1=Wl) ----
#pragma unroll
    for (int p = 0; p < 8; p++) {
        const int c = p >> 1;
        const int kind = p & 1;
        __syncthreads();                       // prev-prev buffer free
        if (p < 7) {
            const int pn = p + 1;
            const int cn = pn >> 1;
            const __nv_bfloat16* src = (pn & 1) ? g_Wl : g_Wh;
            uint32_t dstb = sb + B_BASE + (uint32_t)((pn & 1 ^ (p & 1) ^ (p & 1)) , 0);
            dstb = sb + B_BASE + (uint32_t)(pn & 1) * B_BUF;
#pragma unroll
            for (int i = 0; i < 8; i++) {
                int idx = tid + i * 256;
                int r = idx >> 5, kc = idx & 31;
                cp_async16(dstb + (uint32_t)(r * SROW + kc * 16),
                           &src[(size_t)(cn * 64 + r) * KIN + kc * 8]);
            }
            cp_commit();
            cp_wait<1>();                      // phase p data arrived
        } else {
            cp_wait<0>();
        }
        __syncthreads();

        const uint32_t bb = sb + B_BASE + (uint32_t)(p & 1) * B_BUF;
        const uint32_t b0a = bb + offB0;
        const uint32_t b1a = bb + offB1;
        const uint32_t ah0 = sb + A_HI + offA0;
        const uint32_t ah1 = sb + A_HI + offA1;
        const uint32_t al0 = sb + A_LO + offA0;
        const uint32_t al1 = sb + A_LO + offA1;

        if (kind == 0) {
#pragma unroll 4
            for (int ks = 0; ks < 16; ks++) {
                const uint32_t kb = (uint32_t)(ks * 32);
                uint32_t Ah0[4], Ah1[4], Al0[4], Al1[4], Bf0[4], Bf1[4];
                ldsm_x4(ah0 + kb, Ah0[0], Ah0[1], Ah0[2], Ah0[3]);
                ldsm_x4(ah1 + kb, Ah1[0], Ah1[1], Ah1[2], Ah1[3]);
                ldsm_x4(al0 + kb, Al0[0], Al0[1], Al0[2], Al0[3]);
                ldsm_x4(al1 + kb, Al1[0], Al1[1], Al1[2], Al1[3]);
                ldsm_x4(b0a + kb, Bf0[0], Bf0[1], Bf0[2], Bf0[3]);
                ldsm_x4(b1a + kb, Bf1[0], Bf1[1], Bf1[2], Bf1[3]);
#pragma unroll
                for (int nt = 0; nt < 4; nt++) {
                    uint32_t b0 = (nt < 2) ? Bf0[2 * nt]     : Bf1[2 * (nt - 2)];
                    uint32_t b1 = (nt < 2) ? Bf0[2 * nt + 1] : Bf1[2 * (nt - 2) + 1];
                    mma_bf16(acc[c][0][nt], Ah0, b0, b1);
                    mma_bf16(acc[c][1][nt], Ah1, b0, b1);
                    mma_bf16(acc[c][0][nt], Al0, b0, b1);
                    mma_bf16(acc[c][1][nt], Al1, b0, b1);
                }
            }
        } else {
#pragma unroll 4
            for (int ks = 0; ks < 16; ks++) {
                const uint32_t kb = (uint32_t)(ks * 32);
                uint32_t Ah0[4], Ah1[4], Bf0[4], Bf1[4];
                ldsm_x4(ah0 + kb, Ah0[0], Ah0[1], Ah0[2], Ah0[3]);
                ldsm_x4(ah1 + kb, Ah1[0], Ah1[1], Ah1[2], Ah1[3]);
                ldsm_x4(b0a + kb, Bf0[0], Bf0[1], Bf0[2], Bf0[3]);
                ldsm_x4(b1a + kb, Bf1[0], Bf1[1], Bf1[2], Bf1[3]);
#pragma unroll
                for (int nt = 0; nt < 4; nt++) {
                    uint32_t b0 = (nt < 2) ? Bf0[2 * nt]     : Bf1[2 * (nt - 2)];
                    uint32_t b1 = (nt < 2) ? Bf0[2 * nt + 1] : Bf1[2 * (nt - 2) + 1];
                    mma_bf16(acc[c][0][nt], Ah0, b0, b1);
                    mma_bf16(acc[c][1][nt], Ah1, b0, b1);
                }
            }
        }
    }
    __syncthreads();

    // ---- LayerNorm stats (reuse B smem region) ----
    float* sSum = (float*)(smem + B_BASE);
    float* sSq  = sSum + 256;
    float* sMu  = sSq + 256;
    float* sRs  = sMu + 128;

#pragma unroll
    for (int mt = 0; mt < 2; mt++)
#pragma unroll
        for (int half = 0; half < 2; half++) {
            float s = 0.f, q = 0.f;
#pragma unroll
            for (int c = 0; c < 4; c++)
#pragma unroll
                for (int nt = 0; nt < 4; nt++)
#pragma unroll
                    for (int j = 0; j < 2; j++) {
                        float v = acc[c][mt][nt][half * 2 + j];
                        s += v; q += v * v;
                    }
            s += __shfl_xor_sync(0xffffffffu, s, 1);
            q += __shfl_xor_sync(0xffffffffu, q, 1);
            s += __shfl_xor_sync(0xffffffffu, s, 2);
            q += __shfl_xor_sync(0xffffffffu, q, 2);
            if (tig == 0) {
                int row = mw + mt * 16 + half * 8 + g;
                sSum[row * 2 + wn] = s;
                sSq[row * 2 + wn]  = q;
            }
        }
    __syncthreads();

    if (tid < 128) {
        float s = sSum[tid * 2] + sSum[tid * 2 + 1];
        float q = sSq[tid * 2] + sSq[tid * 2 + 1];
        float mu = s * (1.0f / OD);
        float var = fmaxf(q * (1.0f / OD) - mu * mu, 0.0f);
        sMu[tid] = mu;
        sRs[tid] = rsqrtf(var + LN_EPS);
    }
    __syncthreads();

    // ---- normalize + affine + ReLU + store ----
#pragma unroll
    for (int mt = 0; mt < 2; mt++)
#pragma unroll
        for (int half = 0; half < 2; half++) {
            int row = mw + mt * 16 + half * 8 + g;
            float mu = sMu[row];
            float rs = sRs[row];
            float* orow = out + (size_t)(rowBase + row) * OD;
#pragma unroll
            for (int c = 0; c < 4; c++)
#pragma unroll
                for (int nt = 0; nt < 4; nt++) {
                    int col = c * 64 + wn * 32 + nt * 8 + tig * 2;
                    float2 gb0 = *(const float2*)&gamma[col];
                    float2 bb0 = *(const float2*)&beta[col];
                    float v0 = acc[c][mt][nt][half * 2 + 0];
                    float v1 = acc[c][mt][nt][half * 2 + 1];
                    float2 r2;
                    r2.x = fmaxf((v0 - mu) * rs * gb0.x + bb0.x, 0.0f);
                    r2.y = fmaxf((v1 - mu) * rs * gb0.y + bb0.y, 0.0f);
                    *(float2*)&orow[col] = r2;
                }
        }
}

// ---------------------------------------------------------------------------
extern "C" void kernel_launch(void* const* d_in, const int* in_sizes, int n_in,
                              void* d_out, int out_size)
{
    const float* pos_x   = (const float*)d_in[0];
    const float* xfeat   = (const float*)d_in[1];
    const int*   batch_x = (const int*)  d_in[2];
    const float* pos_y   = (const float*)d_in[3];
    const float* yfeat   = (const float*)d_in[4];
    const int*   batch_y = (const int*)  d_in[5];
    const float* W       = (const float*)d_in[6];
    const float* gamma   = (const float*)d_in[7];
    const float* beta    = (const float*)d_in[8];
    float* out = (float*)d_out;

    prep_kernel<<<KNN_BLOCKS + W_BLOCKS, 256>>>(pos_x, xfeat, batch_x,
                                                pos_y, yfeat, batch_y, W);

    cudaFuncSetAttribute(gemm_mma_kernel,
                         cudaFuncAttributeMaxDynamicSharedMemorySize, SM_TOTAL);
    gemm_mma_kernel<<<NY / 128, 256, SM_TOTAL>>>(gamma, beta, out);
}